// round 7
// baseline (speedup 1.0000x reference)
#include <cuda_runtime.h>
#include <cuda_bf16.h>
#include <cstdint>

#define DD 128
#define MAXN 50016
#define MAXE 800000
#define SCAN_CHUNK 2048
#define MAXP ((MAXN + SCAN_CHUNK - 1) / SCAN_CHUNK)

// ---------------- scratch (device globals; allocation-free) ----------------
__device__ __align__(16) float g_a1[(size_t)MAXN * DD];  // ping
__device__ __align__(16) float g_a2[(size_t)MAXN * DD];  // pong
__device__ __align__(16) __nv_bfloat16 g_whi[3 * DD * DD];
__device__ __align__(16) __nv_bfloat16 g_wlo[3 * DD * DD];
__device__ float g_dinv[MAXN];
__device__ int   g_cnt[MAXN];
__device__ int   g_off[MAXN + 1];
__device__ int   g_cur[MAXN];
__device__ int   g_esrc[MAXE];
__device__ float g_ew[MAXE];
__device__ int   g_partial[MAXP + 1];

// ---------------- helpers ----------------
__device__ __forceinline__ void split_bf16(float f, __nv_bfloat16& h, __nv_bfloat16& l) {
    h = __float2bfloat16(f);
    l = __float2bfloat16(f - __bfloat162float(h));
}
__device__ __forceinline__ void split2(float2 f, uint32_t& hu, uint32_t& lu) {
    __nv_bfloat16 h0, l0, h1, l1;
    split_bf16(f.x, h0, l0);
    split_bf16(f.y, h1, l1);
    union { __nv_bfloat162 b; uint32_t u; } c;
    c.b = __halves2bfloat162(h0, h1);
    hu = c.u;
    c.b = __halves2bfloat162(l0, l1);
    lu = c.u;
}

// ---------------------------------------------------------------------------
// init: zero cnt + transpose/split all 3 weight matrices (one launch)
// ---------------------------------------------------------------------------
__global__ __launch_bounds__(256) void init_kernel(int* __restrict__ cnt, int n, int nzb,
                                                   const float* __restrict__ W1,
                                                   const float* __restrict__ W2,
                                                   const float* __restrict__ W3,
                                                   __nv_bfloat16* __restrict__ whi,
                                                   __nv_bfloat16* __restrict__ wlo) {
    if ((int)blockIdx.x < nzb) {
        int i = blockIdx.x * 256 + threadIdx.x;
        if (i < n) cnt[i] = 0;
    } else {
        int i = (blockIdx.x - nzb) * 256 + threadIdx.x;
        if (i < 3 * DD * DD) {
            int layer = i / (DD * DD);
            int j = i - layer * (DD * DD);
            const float* W = (layer == 0) ? W1 : ((layer == 1) ? W2 : W3);
            int nn = j >> 7, kk = j & 127;
            float v = W[kk * DD + nn];
            __nv_bfloat16 h, l;
            split_bf16(v, h, l);
            whi[i] = h;
            wlo[i] = l;
        }
    }
}

__global__ void count_kernel(const int* __restrict__ dst, int* __restrict__ cnt, int E) {
    int e = blockIdx.x * blockDim.x + threadIdx.x;
    if (e < E) atomicAdd(&cnt[dst[e]], 1);
}

// Phase 1: per-block sums
__global__ __launch_bounds__(256) void scan_p1_kernel(const int* __restrict__ cnt,
                                                      int* __restrict__ partial, int n) {
    __shared__ int warp_sums[8];
    int t = threadIdx.x;
    int base = blockIdx.x * SCAN_CHUNK + t * 8;
    int s = 0;
#pragma unroll
    for (int j = 0; j < 8; ++j) {
        int i = base + j;
        if (i < n) s += cnt[i];
    }
#pragma unroll
    for (int o = 16; o > 0; o >>= 1) s += __shfl_down_sync(0xffffffffu, s, o);
    if ((t & 31) == 0) warp_sums[t >> 5] = s;
    __syncthreads();
    if (t < 8) {
        int v = warp_sums[t];
#pragma unroll
        for (int o = 4; o > 0; o >>= 1) v += __shfl_down_sync(0xffu, v, o);
        if (t == 0) partial[blockIdx.x] = v;
    }
}

// Phase 3 (merged top scan, warp-shuffle based: 2 barriers)
__global__ __launch_bounds__(256) void scan_p3_kernel(const int* __restrict__ cnt,
                                                      const int* __restrict__ partial,
                                                      int* __restrict__ off,
                                                      int* __restrict__ cur,
                                                      float* __restrict__ dinv, int n, int np) {
    __shared__ int s_base;
    __shared__ int wsum[8];
    int t = threadIdx.x;
    int lane = t & 31;
    int warp = t >> 5;
    if (t < 32) {
        int v = (t < np) ? partial[t] : 0;
#pragma unroll
        for (int o = 1; o < 32; o <<= 1) {
            int u = __shfl_up_sync(0xffffffffu, v, o);
            if (t >= o) v += u;
        }
        int srcl = (int)blockIdx.x - 1;
        int excl = __shfl_sync(0xffffffffu, v, (srcl < 0) ? 0 : srcl);
        if (t == 0) s_base = (blockIdx.x == 0) ? 0 : excl;
        if (blockIdx.x == 0 && t == 31) off[n] = v;
    }

    int base = blockIdx.x * SCAN_CHUNK + t * 8;
    int c[8];
    int s = 0;
#pragma unroll
    for (int j = 0; j < 8; ++j) {
        int i = base + j;
        c[j] = (i < n) ? cnt[i] : 0;
        s += c[j];
    }
    int incl = s;
#pragma unroll
    for (int o = 1; o < 32; o <<= 1) {
        int u = __shfl_up_sync(0xffffffffu, incl, o);
        if (lane >= o) incl += u;
    }
    if (lane == 31) wsum[warp] = incl;
    __syncthreads();
    if (t < 8) {
        int v = wsum[t];
#pragma unroll
        for (int o = 1; o < 8; o <<= 1) {
            int u = __shfl_up_sync(0xffu, v, o);
            if (t >= o) v += u;
        }
        wsum[t] = v - wsum[t];
    }
    __syncthreads();
    int run = s_base + wsum[warp] + (incl - s);
#pragma unroll
    for (int j = 0; j < 8; ++j) {
        int i = base + j;
        if (i < n) {
            off[i] = run;
            cur[i] = run;
            dinv[i] = rsqrtf((float)(c[j] + 1));
            run += c[j];
        }
    }
}

__global__ void fill_kernel(const int* __restrict__ src, const int* __restrict__ dst,
                            const float* __restrict__ dinv, int* __restrict__ cur,
                            int* __restrict__ esrc, float* __restrict__ ew, int E) {
    int e = blockIdx.x * blockDim.x + threadIdx.x;
    if (e >= E) return;
    int s = src[e];
    int d = dst[e];
    int pos = atomicAdd(&cur[d], 1);
    esrc[pos] = s;
    ew[pos] = dinv[s] * dinv[d];
}

// ---------------------------------------------------------------------------
// Fused layer kernel (agg -> smem A -> split-bf16 HMMA -> bias/ReLU).
// NOTE: input h and output C MUST NOT alias (ping-pong buffers).
// ---------------------------------------------------------------------------
#define BSTRIDE_U32 68
#define ASTRIDE_F32 132
#define SM_BH 0
#define SM_BL (128 * BSTRIDE_U32)
#define SM_A  (2 * 128 * BSTRIDE_U32)
#define FUSED_SMEM ((2 * 128 * BSTRIDE_U32 + 128 * ASTRIDE_F32) * 4)

__device__ __forceinline__ void mma_bf16(float* c, const uint32_t* a, uint32_t b0, uint32_t b1) {
    asm volatile(
        "mma.sync.aligned.m16n8k16.row.col.f32.bf16.bf16.f32 "
        "{%0,%1,%2,%3}, {%4,%5,%6,%7}, {%8,%9}, {%0,%1,%2,%3};"
        : "+f"(c[0]), "+f"(c[1]), "+f"(c[2]), "+f"(c[3])
        : "r"(a[0]), "r"(a[1]), "r"(a[2]), "r"(a[3]), "r"(b0), "r"(b1));
}

template <int RELU>
__global__ __launch_bounds__(256) void fused_layer_kernel(
    const float* __restrict__ h,
    const float* __restrict__ dinv, const int* __restrict__ off,
    const int* __restrict__ esrc, const float* __restrict__ ew,
    const __nv_bfloat16* __restrict__ Whi, const __nv_bfloat16* __restrict__ Wlo,
    const float* __restrict__ bias, float* __restrict__ C, int n) {
    extern __shared__ uint32_t sm[];
    uint32_t* sBh = sm + SM_BH;
    uint32_t* sBl = sm + SM_BL;
    float* sA = (float*)(sm + SM_A);

    const int tid = threadIdx.x;
    const int warp = tid >> 5;
    const int lane = tid & 31;
    const int quad = lane >> 2;
    const int tq = lane & 3;
    const int row0 = blockIdx.x * 128;

    // ---- stage W hi/lo ----
    const uint32_t* Wh32 = (const uint32_t*)Whi;
    const uint32_t* Wl32 = (const uint32_t*)Wlo;
#pragma unroll
    for (int i = tid; i < 128 * 64; i += 256) {
        int r = i >> 6, kp = i & 63;
        sBh[r * BSTRIDE_U32 + kp] = Wh32[i];
        sBl[r * BSTRIDE_U32 + kp] = Wl32[i];
    }

    // ---- aggregate 16 nodes per warp into sA ----
    const float4* __restrict__ h4 = (const float4*)h;
#pragma unroll 1
    for (int i = 0; i < 16; ++i) {
        int r = warp * 16 + i;
        int node = row0 + r;
        float4 acc = make_float4(0.f, 0.f, 0.f, 0.f);
        if (node < n) {
            float di = dinv[node];
            float wself = di * di;
            float4 self = h4[(size_t)node * 32 + lane];
            acc.x = wself * self.x;
            acc.y = wself * self.y;
            acc.z = wself * self.z;
            acc.w = wself * self.w;
            int e = off[node], e1 = off[node + 1];
            for (; e + 3 < e1; e += 4) {
                int s0 = __ldg(&esrc[e]);
                int s1 = __ldg(&esrc[e + 1]);
                int s2 = __ldg(&esrc[e + 2]);
                int s3 = __ldg(&esrc[e + 3]);
                float w0 = __ldg(&ew[e]);
                float w1 = __ldg(&ew[e + 1]);
                float w2 = __ldg(&ew[e + 2]);
                float w3 = __ldg(&ew[e + 3]);
                float4 v0 = h4[(size_t)s0 * 32 + lane];
                float4 v1 = h4[(size_t)s1 * 32 + lane];
                float4 v2 = h4[(size_t)s2 * 32 + lane];
                float4 v3 = h4[(size_t)s3 * 32 + lane];
                acc.x = fmaf(w0, v0.x, acc.x); acc.y = fmaf(w0, v0.y, acc.y);
                acc.z = fmaf(w0, v0.z, acc.z); acc.w = fmaf(w0, v0.w, acc.w);
                acc.x = fmaf(w1, v1.x, acc.x); acc.y = fmaf(w1, v1.y, acc.y);
                acc.z = fmaf(w1, v1.z, acc.z); acc.w = fmaf(w1, v1.w, acc.w);
                acc.x = fmaf(w2, v2.x, acc.x); acc.y = fmaf(w2, v2.y, acc.y);
                acc.z = fmaf(w2, v2.z, acc.z); acc.w = fmaf(w2, v2.w, acc.w);
                acc.x = fmaf(w3, v3.x, acc.x); acc.y = fmaf(w3, v3.y, acc.y);
                acc.z = fmaf(w3, v3.z, acc.z); acc.w = fmaf(w3, v3.w, acc.w);
            }
            for (; e < e1; ++e) {
                int s0 = __ldg(&esrc[e]);
                float w0 = __ldg(&ew[e]);
                float4 v0 = h4[(size_t)s0 * 32 + lane];
                acc.x = fmaf(w0, v0.x, acc.x); acc.y = fmaf(w0, v0.y, acc.y);
                acc.z = fmaf(w0, v0.z, acc.z); acc.w = fmaf(w0, v0.w, acc.w);
            }
        }
        float* ap = sA + r * ASTRIDE_F32 + lane * 4;
        ap[0] = acc.x; ap[1] = acc.y; ap[2] = acc.z; ap[3] = acc.w;
    }
    __syncthreads();

    // ---- MMA phase ----
    const int r_lo = warp * 16 + quad;
    const int r_hi = r_lo + 8;
    const bool ok_lo = (row0 + r_lo) < n;
    const bool ok_hi = (row0 + r_hi) < n;

    float acc[16][4];
#pragma unroll
    for (int t = 0; t < 16; ++t)
#pragma unroll
        for (int j = 0; j < 4; ++j) acc[t][j] = 0.f;

#pragma unroll
    for (int ks = 0; ks < 8; ++ks) {
        const int k0 = ks * 16;
        uint32_t ah[4], al[4];
        {
            const float* pa_lo = sA + r_lo * ASTRIDE_F32 + k0 + 2 * tq;
            const float* pa_hi = sA + r_hi * ASTRIDE_F32 + k0 + 2 * tq;
            float2 f0 = *(const float2*)(pa_lo);
            float2 f1 = *(const float2*)(pa_hi);
            float2 f2 = *(const float2*)(pa_lo + 8);
            float2 f3 = *(const float2*)(pa_hi + 8);
            split2(f0, ah[0], al[0]);
            split2(f1, ah[1], al[1]);
            split2(f2, ah[2], al[2]);
            split2(f3, ah[3], al[3]);
        }
        const int kbase = (k0 >> 1) + tq;
#pragma unroll
        for (int nt = 0; nt < 16; ++nt) {
            int brow = nt * 8 + quad;
            uint32_t bh0 = sBh[brow * BSTRIDE_U32 + kbase];
            uint32_t bh1 = sBh[brow * BSTRIDE_U32 + kbase + 4];
            uint32_t bl0 = sBl[brow * BSTRIDE_U32 + kbase];
            uint32_t bl1 = sBl[brow * BSTRIDE_U32 + kbase + 4];
            mma_bf16(acc[nt], ah, bh0, bh1);
            mma_bf16(acc[nt], ah, bl0, bl1);
            mma_bf16(acc[nt], al, bh0, bh1);
        }
    }

#pragma unroll
    for (int nt = 0; nt < 16; ++nt) {
        int col = nt * 8 + 2 * tq;
        float2 bv = *(const float2*)(bias + col);
        float c0 = acc[nt][0] + bv.x, c1 = acc[nt][1] + bv.y;
        float c2 = acc[nt][2] + bv.x, c3 = acc[nt][3] + bv.y;
        if (RELU) {
            c0 = fmaxf(c0, 0.f); c1 = fmaxf(c1, 0.f);
            c2 = fmaxf(c2, 0.f); c3 = fmaxf(c3, 0.f);
        }
        if (ok_lo) *(float2*)(C + (size_t)(row0 + r_lo) * DD + col) = make_float2(c0, c1);
        if (ok_hi) *(float2*)(C + (size_t)(row0 + r_hi) * DD + col) = make_float2(c2, c3);
    }
}

// ---------------------------------------------------------------------------
// Launch: x -> a1 -> a2 -> out (no aliasing between fused layers)
// ---------------------------------------------------------------------------
extern "C" void kernel_launch(void* const* d_in, const int* in_sizes, int n_in,
                              void* d_out, int out_size) {
    const float* x  = (const float*)d_in[0];
    const int*   ei = (const int*)d_in[1];
    const float* W1 = (const float*)d_in[2];
    const float* b1 = (const float*)d_in[3];
    const float* W2 = (const float*)d_in[4];
    const float* b2 = (const float*)d_in[5];
    const float* W3 = (const float*)d_in[6];
    const float* b3 = (const float*)d_in[7];

    int n = in_sizes[0] / DD;
    int E = in_sizes[1] / 2;
    const int* src = ei;
    const int* dst = ei + E;

    float *a1, *a2, *dinv, *ew;
    __nv_bfloat16 *whi, *wlo;
    int *cnt, *off, *cur, *esrc, *partial;
    cudaGetSymbolAddress((void**)&a1, g_a1);
    cudaGetSymbolAddress((void**)&a2, g_a2);
    cudaGetSymbolAddress((void**)&whi, g_whi);
    cudaGetSymbolAddress((void**)&wlo, g_wlo);
    cudaGetSymbolAddress((void**)&dinv, g_dinv);
    cudaGetSymbolAddress((void**)&cnt, g_cnt);
    cudaGetSymbolAddress((void**)&off, g_off);
    cudaGetSymbolAddress((void**)&cur, g_cur);
    cudaGetSymbolAddress((void**)&esrc, g_esrc);
    cudaGetSymbolAddress((void**)&ew, g_ew);
    cudaGetSymbolAddress((void**)&partial, g_partial);

    float* outp = (float*)d_out;

    cudaFuncSetAttribute(fused_layer_kernel<0>, cudaFuncAttributeMaxDynamicSharedMemorySize,
                         FUSED_SMEM);
    cudaFuncSetAttribute(fused_layer_kernel<1>, cudaFuncAttributeMaxDynamicSharedMemorySize,
                         FUSED_SMEM);

    int tb = 256;
    int np = (n + SCAN_CHUNK - 1) / SCAN_CHUNK;
    int nzb = (n + 255) / 256;
    int wsb = (3 * DD * DD + 255) / 256;

    // --- preprocess + weight prep (5 launches) ---
    init_kernel<<<nzb + wsb, 256>>>(cnt, n, nzb, W1, W2, W3, whi, wlo);
    count_kernel<<<(E + tb - 1) / tb, tb>>>(dst, cnt, E);
    scan_p1_kernel<<<np, 256>>>(cnt, partial, n);
    scan_p3_kernel<<<np, 256>>>(cnt, partial, off, cur, dinv, n, np);
    fill_kernel<<<(E + tb - 1) / tb, tb>>>(src, dst, dinv, cur, esrc, ew, E);

    int grid = (n + 127) / 128;

    // 3 fused layers, ping-pong (never alias input/output)
    fused_layer_kernel<1><<<grid, 256, FUSED_SMEM>>>(x, dinv, off, esrc, ew, whi, wlo, b1,
                                                     a1, n);
    fused_layer_kernel<1><<<grid, 256, FUSED_SMEM>>>(a1, dinv, off, esrc, ew, whi + DD * DD,
                                                     wlo + DD * DD, b2, a2, n);
    fused_layer_kernel<0><<<grid, 256, FUSED_SMEM>>>(a2, dinv, off, esrc, ew,
                                                     whi + 2 * DD * DD, wlo + 2 * DD * DD, b3,
                                                     outp, n);
}

// round 8
// speedup vs baseline: 2.1871x; 2.1871x over previous
#include <cuda_runtime.h>
#include <cuda_bf16.h>
#include <cstdint>

#define DD 128
#define MAXN 50016
#define MAXE 800000
#define SCAN_CHUNK 2048
#define MAXP ((MAXN + SCAN_CHUNK - 1) / SCAN_CHUNK)

// ---------------- scratch (device globals; allocation-free) ----------------
__device__ __align__(16) float g_y[(size_t)MAXN * DD];    // post-agg
__device__ __align__(16) float g_act[(size_t)MAXN * DD];  // post-gemm activation
__device__ __align__(16) __nv_bfloat16 g_whi[3 * DD * DD];
__device__ __align__(16) __nv_bfloat16 g_wlo[3 * DD * DD];
__device__ float g_dinv[MAXN];
__device__ __align__(16) int g_cnt[MAXN];
__device__ int   g_off[MAXN + 1];
__device__ int   g_cur[MAXN];
__device__ int   g_esrc[MAXE];
__device__ float g_ew[MAXE];
__device__ int   g_partial[MAXP + 1];

// ---------------- helpers ----------------
__device__ __forceinline__ void split_bf16(float f, __nv_bfloat16& h, __nv_bfloat16& l) {
    h = __float2bfloat16(f);
    l = __float2bfloat16(f - __bfloat162float(h));
}
__device__ __forceinline__ void split2(float2 f, uint32_t& hu, uint32_t& lu) {
    __nv_bfloat16 h0, l0, h1, l1;
    split_bf16(f.x, h0, l0);
    split_bf16(f.y, h1, l1);
    union { __nv_bfloat162 b; uint32_t u; } c;
    c.b = __halves2bfloat162(h0, h1);
    hu = c.u;
    c.b = __halves2bfloat162(l0, l1);
    lu = c.u;
}

// ---------------------------------------------------------------------------
// init: zero cnt + transpose/split all 3 weight matrices (one launch)
// ---------------------------------------------------------------------------
__global__ __launch_bounds__(256) void init_kernel(int* __restrict__ cnt, int n, int nzb,
                                                   const float* __restrict__ W1,
                                                   const float* __restrict__ W2,
                                                   const float* __restrict__ W3,
                                                   __nv_bfloat16* __restrict__ whi,
                                                   __nv_bfloat16* __restrict__ wlo) {
    if ((int)blockIdx.x < nzb) {
        int i = blockIdx.x * 256 + threadIdx.x;
        if (i < n) cnt[i] = 0;
    } else {
        int i = (blockIdx.x - nzb) * 256 + threadIdx.x;
        if (i < 3 * DD * DD) {
            int layer = i / (DD * DD);
            int j = i - layer * (DD * DD);
            const float* W = (layer == 0) ? W1 : ((layer == 1) ? W2 : W3);
            int nn = j >> 7, kk = j & 127;
            float v = W[kk * DD + nn];
            __nv_bfloat16 h, l;
            split_bf16(v, h, l);
            whi[i] = h;
            wlo[i] = l;
        }
    }
}

__global__ void count_kernel(const int* __restrict__ dst, int* __restrict__ cnt, int E) {
    int e = blockIdx.x * blockDim.x + threadIdx.x;
    if (e < E) atomicAdd(&cnt[dst[e]], 1);
}

// Phase 1: per-block sums. 1024 threads x 2 ints (int2 loads).
__global__ __launch_bounds__(1024) void scan_p1_kernel(const int* __restrict__ cnt,
                                                       int* __restrict__ partial, int n) {
    __shared__ int wsum[32];
    int t = threadIdx.x;
    int i0 = blockIdx.x * SCAN_CHUNK + t * 2;
    int s = 0;
    if (i0 + 1 < n) {
        int2 v = *(const int2*)(cnt + i0);
        s = v.x + v.y;
    } else if (i0 < n) {
        s = cnt[i0];
    }
#pragma unroll
    for (int o = 16; o > 0; o >>= 1) s += __shfl_down_sync(0xffffffffu, s, o);
    if ((t & 31) == 0) wsum[t >> 5] = s;
    __syncthreads();
    if (t < 32) {
        int v = wsum[t];
#pragma unroll
        for (int o = 16; o > 0; o >>= 1) v += __shfl_down_sync(0xffffffffu, v, o);
        if (t == 0) partial[blockIdx.x] = v;
    }
}

// Phase 3: merged top scan + per-block rescan. 1024 threads x 2 ints.
__global__ __launch_bounds__(1024) void scan_p3_kernel(const int* __restrict__ cnt,
                                                       const int* __restrict__ partial,
                                                       int* __restrict__ off,
                                                       int* __restrict__ cur,
                                                       float* __restrict__ dinv, int n, int np) {
    __shared__ int s_base;
    __shared__ int wsum[32];
    int t = threadIdx.x;
    int lane = t & 31;
    int warp = t >> 5;

    if (t < 32) {
        int v = (t < np) ? partial[t] : 0;
#pragma unroll
        for (int o = 1; o < 32; o <<= 1) {
            int u = __shfl_up_sync(0xffffffffu, v, o);
            if (t >= o) v += u;
        }
        int srcl = (int)blockIdx.x - 1;
        int excl = __shfl_sync(0xffffffffu, v, (srcl < 0) ? 0 : srcl);
        if (t == 0) s_base = (blockIdx.x == 0) ? 0 : excl;
        if (blockIdx.x == 0 && t == 31) off[n] = v;
    }

    int i0 = blockIdx.x * SCAN_CHUNK + t * 2;
    int c0 = 0, c1 = 0;
    if (i0 + 1 < n) {
        int2 v = *(const int2*)(cnt + i0);
        c0 = v.x;
        c1 = v.y;
    } else if (i0 < n) {
        c0 = cnt[i0];
    }
    int s = c0 + c1;
    int incl = s;
#pragma unroll
    for (int o = 1; o < 32; o <<= 1) {
        int u = __shfl_up_sync(0xffffffffu, incl, o);
        if (lane >= o) incl += u;
    }
    if (lane == 31) wsum[warp] = incl;
    __syncthreads();
    if (t < 32) {
        int v = wsum[t];
        int orig = v;
#pragma unroll
        for (int o = 1; o < 32; o <<= 1) {
            int u = __shfl_up_sync(0xffffffffu, v, o);
            if (t >= o) v += u;
        }
        wsum[t] = v - orig;  // exclusive prefix of warp sums
    }
    __syncthreads();
    int run = s_base + wsum[warp] + (incl - s);
    if (i0 < n) {
        off[i0] = run;
        cur[i0] = run;
        dinv[i0] = rsqrtf((float)(c0 + 1));
        run += c0;
        if (i0 + 1 < n) {
            off[i0 + 1] = run;
            cur[i0 + 1] = run;
            dinv[i0 + 1] = rsqrtf((float)(c1 + 1));
        }
    }
}

__global__ void fill_kernel(const int* __restrict__ src, const int* __restrict__ dst,
                            const float* __restrict__ dinv, int* __restrict__ cur,
                            int* __restrict__ esrc, float* __restrict__ ew, int E) {
    int e = blockIdx.x * blockDim.x + threadIdx.x;
    if (e >= E) return;
    int s = src[e];
    int d = dst[e];
    int pos = atomicAdd(&cur[d], 1);
    esrc[pos] = s;
    ew[pos] = dinv[s] * dinv[d];
}

// ---------------------------------------------------------------------------
// Aggregation (pure): y[i] = dinv[i]^2 * h[i] + sum_e w_e * h[src_e]
// One warp per node, 4-edge unroll. High occupancy = the MLP source.
// ---------------------------------------------------------------------------
__global__ __launch_bounds__(256) void agg_kernel(const float* __restrict__ h,
                                                  const float* __restrict__ dinv,
                                                  const int* __restrict__ off,
                                                  const int* __restrict__ esrc,
                                                  const float* __restrict__ ew,
                                                  float* __restrict__ out, int n) {
    int node = (blockIdx.x * blockDim.x + threadIdx.x) >> 5;
    int lane = threadIdx.x & 31;
    if (node >= n) return;

    const float4* __restrict__ h4 = (const float4*)h;
    float di = dinv[node];
    float wself = di * di;
    float4 self = h4[(size_t)node * 32 + lane];
    float4 acc;
    acc.x = wself * self.x;
    acc.y = wself * self.y;
    acc.z = wself * self.z;
    acc.w = wself * self.w;

    int e = off[node], e1 = off[node + 1];
    for (; e + 3 < e1; e += 4) {
        int s0 = __ldg(&esrc[e]);
        int s1 = __ldg(&esrc[e + 1]);
        int s2 = __ldg(&esrc[e + 2]);
        int s3 = __ldg(&esrc[e + 3]);
        float w0 = __ldg(&ew[e]);
        float w1 = __ldg(&ew[e + 1]);
        float w2 = __ldg(&ew[e + 2]);
        float w3 = __ldg(&ew[e + 3]);
        float4 v0 = h4[(size_t)s0 * 32 + lane];
        float4 v1 = h4[(size_t)s1 * 32 + lane];
        float4 v2 = h4[(size_t)s2 * 32 + lane];
        float4 v3 = h4[(size_t)s3 * 32 + lane];
        acc.x = fmaf(w0, v0.x, acc.x); acc.y = fmaf(w0, v0.y, acc.y);
        acc.z = fmaf(w0, v0.z, acc.z); acc.w = fmaf(w0, v0.w, acc.w);
        acc.x = fmaf(w1, v1.x, acc.x); acc.y = fmaf(w1, v1.y, acc.y);
        acc.z = fmaf(w1, v1.z, acc.z); acc.w = fmaf(w1, v1.w, acc.w);
        acc.x = fmaf(w2, v2.x, acc.x); acc.y = fmaf(w2, v2.y, acc.y);
        acc.z = fmaf(w2, v2.z, acc.z); acc.w = fmaf(w2, v2.w, acc.w);
        acc.x = fmaf(w3, v3.x, acc.x); acc.y = fmaf(w3, v3.y, acc.y);
        acc.z = fmaf(w3, v3.z, acc.z); acc.w = fmaf(w3, v3.w, acc.w);
    }
    for (; e < e1; ++e) {
        int s0 = __ldg(&esrc[e]);
        float w0 = __ldg(&ew[e]);
        float4 v0 = h4[(size_t)s0 * 32 + lane];
        acc.x = fmaf(w0, v0.x, acc.x); acc.y = fmaf(w0, v0.y, acc.y);
        acc.z = fmaf(w0, v0.z, acc.z); acc.w = fmaf(w0, v0.w, acc.w);
    }
    ((float4*)out)[(size_t)node * 32 + lane] = acc;
}

// ---------------------------------------------------------------------------
// HMMA split-bf16 GEMM + fused bias/ReLU epilogue (round-5 proven version)
// ---------------------------------------------------------------------------
#define BSTRIDE_U32 68  // 136 bf16 per row: conflict-free B-frag LDS

__device__ __forceinline__ void mma_bf16(float* c, const uint32_t* a, uint32_t b0, uint32_t b1) {
    asm volatile(
        "mma.sync.aligned.m16n8k16.row.col.f32.bf16.bf16.f32 "
        "{%0,%1,%2,%3}, {%4,%5,%6,%7}, {%8,%9}, {%0,%1,%2,%3};"
        : "+f"(c[0]), "+f"(c[1]), "+f"(c[2]), "+f"(c[3])
        : "r"(a[0]), "r"(a[1]), "r"(a[2]), "r"(a[3]), "r"(b0), "r"(b1));
}

template <int RELU>
__global__ __launch_bounds__(256) void gemm_hmma_kernel(
    const float* __restrict__ A,
    const __nv_bfloat16* __restrict__ Whi, const __nv_bfloat16* __restrict__ Wlo,
    const float* __restrict__ bias, float* __restrict__ C, int n) {
    extern __shared__ uint32_t sB[];
    uint32_t* sBh = sB;
    uint32_t* sBl = sB + 128 * BSTRIDE_U32;

    const int tid = threadIdx.x;
    const int warp = tid >> 5;
    const int lane = tid & 31;
    const int quad = lane >> 2;
    const int tq = lane & 3;
    const int row0 = blockIdx.x * 128;

    const uint32_t* Wh32 = (const uint32_t*)Whi;
    const uint32_t* Wl32 = (const uint32_t*)Wlo;
#pragma unroll
    for (int i = tid; i < 128 * 64; i += 256) {
        int r = i >> 6, kp = i & 63;
        sBh[r * BSTRIDE_U32 + kp] = Wh32[i];
        sBl[r * BSTRIDE_U32 + kp] = Wl32[i];
    }
    __syncthreads();

    const int row_lo = row0 + warp * 16 + quad;
    const int row_hi = row_lo + 8;
    const bool ok_lo = row_lo < n;
    const bool ok_hi = row_hi < n;

    float acc[16][4];
#pragma unroll
    for (int t = 0; t < 16; ++t)
#pragma unroll
        for (int j = 0; j < 4; ++j) acc[t][j] = 0.f;

#pragma unroll
    for (int ks = 0; ks < 8; ++ks) {
        const int k0 = ks * 16;
        uint32_t ah[4], al[4];
        {
            const float2 z2 = make_float2(0.f, 0.f);
            size_t base_lo = (size_t)row_lo * DD + k0 + 2 * tq;
            size_t base_hi = (size_t)row_hi * DD + k0 + 2 * tq;
            float2 f0 = ok_lo ? *(const float2*)(A + base_lo) : z2;
            float2 f1 = ok_hi ? *(const float2*)(A + base_hi) : z2;
            float2 f2 = ok_lo ? *(const float2*)(A + base_lo + 8) : z2;
            float2 f3 = ok_hi ? *(const float2*)(A + base_hi + 8) : z2;
            split2(f0, ah[0], al[0]);
            split2(f1, ah[1], al[1]);
            split2(f2, ah[2], al[2]);
            split2(f3, ah[3], al[3]);
        }
        const int kbase = (k0 >> 1) + tq;
#pragma unroll
        for (int nt = 0; nt < 16; ++nt) {
            int brow = nt * 8 + quad;
            uint32_t bh0 = sBh[brow * BSTRIDE_U32 + kbase];
            uint32_t bh1 = sBh[brow * BSTRIDE_U32 + kbase + 4];
            uint32_t bl0 = sBl[brow * BSTRIDE_U32 + kbase];
            uint32_t bl1 = sBl[brow * BSTRIDE_U32 + kbase + 4];
            mma_bf16(acc[nt], ah, bh0, bh1);
            mma_bf16(acc[nt], ah, bl0, bl1);
            mma_bf16(acc[nt], al, bh0, bh1);
        }
    }

#pragma unroll
    for (int nt = 0; nt < 16; ++nt) {
        int col = nt * 8 + 2 * tq;
        float2 bv = *(const float2*)(bias + col);
        float c0 = acc[nt][0] + bv.x, c1 = acc[nt][1] + bv.y;
        float c2 = acc[nt][2] + bv.x, c3 = acc[nt][3] + bv.y;
        if (RELU) {
            c0 = fmaxf(c0, 0.f); c1 = fmaxf(c1, 0.f);
            c2 = fmaxf(c2, 0.f); c3 = fmaxf(c3, 0.f);
        }
        if (ok_lo) *(float2*)(C + (size_t)row_lo * DD + col) = make_float2(c0, c1);
        if (ok_hi) *(float2*)(C + (size_t)row_hi * DD + col) = make_float2(c2, c3);
    }
}

// ---------------------------------------------------------------------------
// Launch: out = (Anorm @ act) @ W + b per layer (round-5 structure)
// ---------------------------------------------------------------------------
extern "C" void kernel_launch(void* const* d_in, const int* in_sizes, int n_in,
                              void* d_out, int out_size) {
    const float* x  = (const float*)d_in[0];
    const int*   ei = (const int*)d_in[1];
    const float* W1 = (const float*)d_in[2];
    const float* b1 = (const float*)d_in[3];
    const float* W2 = (const float*)d_in[4];
    const float* b2 = (const float*)d_in[5];
    const float* W3 = (const float*)d_in[6];
    const float* b3 = (const float*)d_in[7];

    int n = in_sizes[0] / DD;
    int E = in_sizes[1] / 2;
    const int* src = ei;
    const int* dst = ei + E;

    float *y, *act, *dinv, *ew;
    __nv_bfloat16 *whi, *wlo;
    int *cnt, *off, *cur, *esrc, *partial;
    cudaGetSymbolAddress((void**)&y, g_y);
    cudaGetSymbolAddress((void**)&act, g_act);
    cudaGetSymbolAddress((void**)&whi, g_whi);
    cudaGetSymbolAddress((void**)&wlo, g_wlo);
    cudaGetSymbolAddress((void**)&dinv, g_dinv);
    cudaGetSymbolAddress((void**)&cnt, g_cnt);
    cudaGetSymbolAddress((void**)&off, g_off);
    cudaGetSymbolAddress((void**)&cur, g_cur);
    cudaGetSymbolAddress((void**)&esrc, g_esrc);
    cudaGetSymbolAddress((void**)&ew, g_ew);
    cudaGetSymbolAddress((void**)&partial, g_partial);

    float* outp = (float*)d_out;

    const int GEMM_SMEM = 2 * 128 * BSTRIDE_U32 * 4;  // 69,632 B
    cudaFuncSetAttribute(gemm_hmma_kernel<0>, cudaFuncAttributeMaxDynamicSharedMemorySize,
                         GEMM_SMEM);
    cudaFuncSetAttribute(gemm_hmma_kernel<1>, cudaFuncAttributeMaxDynamicSharedMemorySize,
                         GEMM_SMEM);

    int tb = 256;
    int np = (n + SCAN_CHUNK - 1) / SCAN_CHUNK;
    int nzb = (n + 255) / 256;
    int wsb = (3 * DD * DD + 255) / 256;

    // --- preprocess + weight prep (5 launches) ---
    init_kernel<<<nzb + wsb, 256>>>(cnt, n, nzb, W1, W2, W3, whi, wlo);
    count_kernel<<<(E + tb - 1) / tb, tb>>>(dst, cnt, E);
    scan_p1_kernel<<<np, 1024>>>(cnt, partial, n);
    scan_p3_kernel<<<np, 1024>>>(cnt, partial, off, cur, dinv, n, np);
    fill_kernel<<<(E + tb - 1) / tb, tb>>>(src, dst, dinv, cur, esrc, ew, E);

    int gemm_grid = (n + 127) / 128;
    int agg_grid = (n + 7) / 8;

    // Layer 1
    agg_kernel<<<agg_grid, 256>>>(x, dinv, off, esrc, ew, y, n);
    gemm_hmma_kernel<1><<<gemm_grid, 256, GEMM_SMEM>>>(y, whi, wlo, b1, act, n);
    // Layer 2
    agg_kernel<<<agg_grid, 256>>>(act, dinv, off, esrc, ew, y, n);
    gemm_hmma_kernel<1><<<gemm_grid, 256, GEMM_SMEM>>>(y, whi + DD * DD, wlo + DD * DD, b2,
                                                       act, n);
    // Layer 3 (no relu) -> d_out
    agg_kernel<<<agg_grid, 256>>>(act, dinv, off, esrc, ew, y, n);
    gemm_hmma_kernel<0><<<gemm_grid, 256, GEMM_SMEM>>>(y, whi + 2 * DD * DD,
                                                       wlo + 2 * DD * DD, b3, outp, n);
}

// round 9
// speedup vs baseline: 2.2430x; 1.0256x over previous
#include <cuda_runtime.h>
#include <cuda_bf16.h>
#include <cuda_fp16.h>
#include <cstdint>

#define DD 128
#define MAXN 50016
#define MAXE 800000
#define SCAN_CHUNK 2048
#define MAXP ((MAXN + SCAN_CHUNK - 1) / SCAN_CHUNK)

// ---------------- scratch (device globals; allocation-free) ----------------
__device__ __align__(16) float g_y[(size_t)MAXN * DD];        // post-agg (fp32)
__device__ __align__(16) __half g_x16[(size_t)MAXN * DD];     // fp16 input copy
__device__ __align__(16) __half g_act16[(size_t)MAXN * DD];   // fp16 activations
__device__ __align__(16) __nv_bfloat16 g_whi[3 * DD * DD];
__device__ __align__(16) __nv_bfloat16 g_wlo[3 * DD * DD];
__device__ float g_dinv[MAXN];
__device__ __align__(16) int g_cnt[MAXN];
__device__ int   g_off[MAXN + 1];
__device__ int   g_cur[MAXN];
__device__ int   g_esrc[MAXE];
__device__ float g_ew[MAXE];
__device__ int   g_partial[MAXP + 1];

// ---------------- helpers ----------------
__device__ __forceinline__ void split_bf16(float f, __nv_bfloat16& h, __nv_bfloat16& l) {
    h = __float2bfloat16(f);
    l = __float2bfloat16(f - __bfloat162float(h));
}
__device__ __forceinline__ void split2(float2 f, uint32_t& hu, uint32_t& lu) {
    __nv_bfloat16 h0, l0, h1, l1;
    split_bf16(f.x, h0, l0);
    split_bf16(f.y, h1, l1);
    union { __nv_bfloat162 b; uint32_t u; } c;
    c.b = __halves2bfloat162(h0, h1);
    hu = c.u;
    c.b = __halves2bfloat162(l0, l1);
    lu = c.u;
}

// ---------------------------------------------------------------------------
// init: zero cnt + transpose/split all 3 weight matrices (one launch)
// ---------------------------------------------------------------------------
__global__ __launch_bounds__(256) void init_kernel(int* __restrict__ cnt, int n, int nzb,
                                                   const float* __restrict__ W1,
                                                   const float* __restrict__ W2,
                                                   const float* __restrict__ W3,
                                                   __nv_bfloat16* __restrict__ whi,
                                                   __nv_bfloat16* __restrict__ wlo) {
    if ((int)blockIdx.x < nzb) {
        int i = blockIdx.x * 256 + threadIdx.x;
        if (i < n) cnt[i] = 0;
    } else {
        int i = (blockIdx.x - nzb) * 256 + threadIdx.x;
        if (i < 3 * DD * DD) {
            int layer = i / (DD * DD);
            int j = i - layer * (DD * DD);
            const float* W = (layer == 0) ? W1 : ((layer == 1) ? W2 : W3);
            int nn = j >> 7, kk = j & 127;
            float v = W[kk * DD + nn];
            __nv_bfloat16 h, l;
            split_bf16(v, h, l);
            whi[i] = h;
            wlo[i] = l;
        }
    }
}

// fp32 -> fp16 copy of x (4 floats per thread)
__global__ __launch_bounds__(256) void convert_x_kernel(const float* __restrict__ x,
                                                        __half* __restrict__ x16, int total4) {
    int i = blockIdx.x * blockDim.x + threadIdx.x;
    if (i >= total4) return;
    float4 v = ((const float4*)x)[i];
    __half2 a = __floats2half2_rn(v.x, v.y);
    __half2 b = __floats2half2_rn(v.z, v.w);
    uint2 u;
    u.x = *(uint32_t*)&a;
    u.y = *(uint32_t*)&b;
    ((uint2*)x16)[i] = u;
}

__global__ void count_kernel(const int* __restrict__ dst, int* __restrict__ cnt, int E) {
    int e = blockIdx.x * blockDim.x + threadIdx.x;
    if (e < E) atomicAdd(&cnt[dst[e]], 1);
}

// Phase 1: per-block sums. 1024 threads x 2 ints (int2 loads).
__global__ __launch_bounds__(1024) void scan_p1_kernel(const int* __restrict__ cnt,
                                                       int* __restrict__ partial, int n) {
    __shared__ int wsum[32];
    int t = threadIdx.x;
    int i0 = blockIdx.x * SCAN_CHUNK + t * 2;
    int s = 0;
    if (i0 + 1 < n) {
        int2 v = *(const int2*)(cnt + i0);
        s = v.x + v.y;
    } else if (i0 < n) {
        s = cnt[i0];
    }
#pragma unroll
    for (int o = 16; o > 0; o >>= 1) s += __shfl_down_sync(0xffffffffu, s, o);
    if ((t & 31) == 0) wsum[t >> 5] = s;
    __syncthreads();
    if (t < 32) {
        int v = wsum[t];
#pragma unroll
        for (int o = 16; o > 0; o >>= 1) v += __shfl_down_sync(0xffffffffu, v, o);
        if (t == 0) partial[blockIdx.x] = v;
    }
}

// Phase 3: merged top scan + per-block rescan. 1024 threads x 2 ints.
__global__ __launch_bounds__(1024) void scan_p3_kernel(const int* __restrict__ cnt,
                                                       const int* __restrict__ partial,
                                                       int* __restrict__ off,
                                                       int* __restrict__ cur,
                                                       float* __restrict__ dinv, int n, int np) {
    __shared__ int s_base;
    __shared__ int wsum[32];
    int t = threadIdx.x;
    int lane = t & 31;
    int warp = t >> 5;

    if (t < 32) {
        int v = (t < np) ? partial[t] : 0;
#pragma unroll
        for (int o = 1; o < 32; o <<= 1) {
            int u = __shfl_up_sync(0xffffffffu, v, o);
            if (t >= o) v += u;
        }
        int srcl = (int)blockIdx.x - 1;
        int excl = __shfl_sync(0xffffffffu, v, (srcl < 0) ? 0 : srcl);
        if (t == 0) s_base = (blockIdx.x == 0) ? 0 : excl;
        if (blockIdx.x == 0 && t == 31) off[n] = v;
    }

    int i0 = blockIdx.x * SCAN_CHUNK + t * 2;
    int c0 = 0, c1 = 0;
    if (i0 + 1 < n) {
        int2 v = *(const int2*)(cnt + i0);
        c0 = v.x;
        c1 = v.y;
    } else if (i0 < n) {
        c0 = cnt[i0];
    }
    int s = c0 + c1;
    int incl = s;
#pragma unroll
    for (int o = 1; o < 32; o <<= 1) {
        int u = __shfl_up_sync(0xffffffffu, incl, o);
        if (lane >= o) incl += u;
    }
    if (lane == 31) wsum[warp] = incl;
    __syncthreads();
    if (t < 32) {
        int v = wsum[t];
        int orig = v;
#pragma unroll
        for (int o = 1; o < 32; o <<= 1) {
            int u = __shfl_up_sync(0xffffffffu, v, o);
            if (t >= o) v += u;
        }
        wsum[t] = v - orig;
    }
    __syncthreads();
    int run = s_base + wsum[warp] + (incl - s);
    if (i0 < n) {
        off[i0] = run;
        cur[i0] = run;
        dinv[i0] = rsqrtf((float)(c0 + 1));
        run += c0;
        if (i0 + 1 < n) {
            off[i0 + 1] = run;
            cur[i0 + 1] = run;
            dinv[i0 + 1] = rsqrtf((float)(c1 + 1));
        }
    }
}

__global__ void fill_kernel(const int* __restrict__ src, const int* __restrict__ dst,
                            const float* __restrict__ dinv, int* __restrict__ cur,
                            int* __restrict__ esrc, float* __restrict__ ew, int E) {
    int e = blockIdx.x * blockDim.x + threadIdx.x;
    if (e >= E) return;
    int s = src[e];
    int d = dst[e];
    int pos = atomicAdd(&cur[d], 1);
    esrc[pos] = s;
    ew[pos] = dinv[s] * dinv[d];
}

// ---------------------------------------------------------------------------
// Aggregation: y[i] = dinv^2 * h[i] + sum_e w_e * h[src_e]; h gathered as fp16
// (256 B/row), accumulated in fp32, written fp32. One warp per node; each lane
// owns 4 features (uint2 = 4 halves).
// ---------------------------------------------------------------------------
__device__ __forceinline__ void fma_h4(float4& acc, float w, uint2 u) {
    __half2 a = *(__half2*)&u.x;
    __half2 b = *(__half2*)&u.y;
    float2 fa = __half22float2(a);
    float2 fb = __half22float2(b);
    acc.x = fmaf(w, fa.x, acc.x);
    acc.y = fmaf(w, fa.y, acc.y);
    acc.z = fmaf(w, fb.x, acc.z);
    acc.w = fmaf(w, fb.y, acc.w);
}

__global__ __launch_bounds__(256) void agg_kernel(const __half* __restrict__ h16,
                                                  const float* __restrict__ dinv,
                                                  const int* __restrict__ off,
                                                  const int* __restrict__ esrc,
                                                  const float* __restrict__ ew,
                                                  float* __restrict__ out, int n) {
    int node = (blockIdx.x * blockDim.x + threadIdx.x) >> 5;
    int lane = threadIdx.x & 31;
    if (node >= n) return;

    const uint2* __restrict__ h2 = (const uint2*)h16;  // 32 uint2 per row
    float di = dinv[node];
    float wself = di * di;
    float4 acc = make_float4(0.f, 0.f, 0.f, 0.f);
    fma_h4(acc, wself, h2[(size_t)node * 32 + lane]);

    int e = off[node], e1 = off[node + 1];
    for (; e + 3 < e1; e += 4) {
        int s0 = __ldg(&esrc[e]);
        int s1 = __ldg(&esrc[e + 1]);
        int s2 = __ldg(&esrc[e + 2]);
        int s3 = __ldg(&esrc[e + 3]);
        float w0 = __ldg(&ew[e]);
        float w1 = __ldg(&ew[e + 1]);
        float w2 = __ldg(&ew[e + 2]);
        float w3 = __ldg(&ew[e + 3]);
        uint2 v0 = h2[(size_t)s0 * 32 + lane];
        uint2 v1 = h2[(size_t)s1 * 32 + lane];
        uint2 v2 = h2[(size_t)s2 * 32 + lane];
        uint2 v3 = h2[(size_t)s3 * 32 + lane];
        fma_h4(acc, w0, v0);
        fma_h4(acc, w1, v1);
        fma_h4(acc, w2, v2);
        fma_h4(acc, w3, v3);
    }
    for (; e < e1; ++e) {
        int s0 = __ldg(&esrc[e]);
        float w0 = __ldg(&ew[e]);
        fma_h4(acc, w0, h2[(size_t)s0 * 32 + lane]);
    }
    ((float4*)out)[(size_t)node * 32 + lane] = acc;
}

// ---------------------------------------------------------------------------
// HMMA split-bf16 GEMM + fused bias/ReLU; output fp16 (mid layers) or fp32.
// ---------------------------------------------------------------------------
#define BSTRIDE_U32 68

__device__ __forceinline__ void mma_bf16(float* c, const uint32_t* a, uint32_t b0, uint32_t b1) {
    asm volatile(
        "mma.sync.aligned.m16n8k16.row.col.f32.bf16.bf16.f32 "
        "{%0,%1,%2,%3}, {%4,%5,%6,%7}, {%8,%9}, {%0,%1,%2,%3};"
        : "+f"(c[0]), "+f"(c[1]), "+f"(c[2]), "+f"(c[3])
        : "r"(a[0]), "r"(a[1]), "r"(a[2]), "r"(a[3]), "r"(b0), "r"(b1));
}

template <int RELU, int F16OUT>
__global__ __launch_bounds__(256) void gemm_hmma_kernel(
    const float* __restrict__ A,
    const __nv_bfloat16* __restrict__ Whi, const __nv_bfloat16* __restrict__ Wlo,
    const float* __restrict__ bias, float* __restrict__ C32,
    __half* __restrict__ C16, int n) {
    extern __shared__ uint32_t sB[];
    uint32_t* sBh = sB;
    uint32_t* sBl = sB + 128 * BSTRIDE_U32;

    const int tid = threadIdx.x;
    const int warp = tid >> 5;
    const int lane = tid & 31;
    const int quad = lane >> 2;
    const int tq = lane & 3;
    const int row0 = blockIdx.x * 128;

    const uint32_t* Wh32 = (const uint32_t*)Whi;
    const uint32_t* Wl32 = (const uint32_t*)Wlo;
#pragma unroll
    for (int i = tid; i < 128 * 64; i += 256) {
        int r = i >> 6, kp = i & 63;
        sBh[r * BSTRIDE_U32 + kp] = Wh32[i];
        sBl[r * BSTRIDE_U32 + kp] = Wl32[i];
    }
    __syncthreads();

    const int row_lo = row0 + warp * 16 + quad;
    const int row_hi = row_lo + 8;
    const bool ok_lo = row_lo < n;
    const bool ok_hi = row_hi < n;

    float acc[16][4];
#pragma unroll
    for (int t = 0; t < 16; ++t)
#pragma unroll
        for (int j = 0; j < 4; ++j) acc[t][j] = 0.f;

#pragma unroll
    for (int ks = 0; ks < 8; ++ks) {
        const int k0 = ks * 16;
        uint32_t ah[4], al[4];
        {
            const float2 z2 = make_float2(0.f, 0.f);
            size_t base_lo = (size_t)row_lo * DD + k0 + 2 * tq;
            size_t base_hi = (size_t)row_hi * DD + k0 + 2 * tq;
            float2 f0 = ok_lo ? *(const float2*)(A + base_lo) : z2;
            float2 f1 = ok_hi ? *(const float2*)(A + base_hi) : z2;
            float2 f2 = ok_lo ? *(const float2*)(A + base_lo + 8) : z2;
            float2 f3 = ok_hi ? *(const float2*)(A + base_hi + 8) : z2;
            split2(f0, ah[0], al[0]);
            split2(f1, ah[1], al[1]);
            split2(f2, ah[2], al[2]);
            split2(f3, ah[3], al[3]);
        }
        const int kbase = (k0 >> 1) + tq;
#pragma unroll
        for (int nt = 0; nt < 16; ++nt) {
            int brow = nt * 8 + quad;
            uint32_t bh0 = sBh[brow * BSTRIDE_U32 + kbase];
            uint32_t bh1 = sBh[brow * BSTRIDE_U32 + kbase + 4];
            uint32_t bl0 = sBl[brow * BSTRIDE_U32 + kbase];
            uint32_t bl1 = sBl[brow * BSTRIDE_U32 + kbase + 4];
            mma_bf16(acc[nt], ah, bh0, bh1);
            mma_bf16(acc[nt], ah, bl0, bl1);
            mma_bf16(acc[nt], al, bh0, bh1);
        }
    }

#pragma unroll
    for (int nt = 0; nt < 16; ++nt) {
        int col = nt * 8 + 2 * tq;
        float2 bv = *(const float2*)(bias + col);
        float c0 = acc[nt][0] + bv.x, c1 = acc[nt][1] + bv.y;
        float c2 = acc[nt][2] + bv.x, c3 = acc[nt][3] + bv.y;
        if (RELU) {
            c0 = fmaxf(c0, 0.f); c1 = fmaxf(c1, 0.f);
            c2 = fmaxf(c2, 0.f); c3 = fmaxf(c3, 0.f);
        }
        if (F16OUT) {
            if (ok_lo) *(__half2*)(C16 + (size_t)row_lo * DD + col) = __floats2half2_rn(c0, c1);
            if (ok_hi) *(__half2*)(C16 + (size_t)row_hi * DD + col) = __floats2half2_rn(c2, c3);
        } else {
            if (ok_lo) *(float2*)(C32 + (size_t)row_lo * DD + col) = make_float2(c0, c1);
            if (ok_hi) *(float2*)(C32 + (size_t)row_hi * DD + col) = make_float2(c2, c3);
        }
    }
}

// ---------------------------------------------------------------------------
// Launch
// ---------------------------------------------------------------------------
extern "C" void kernel_launch(void* const* d_in, const int* in_sizes, int n_in,
                              void* d_out, int out_size) {
    const float* x  = (const float*)d_in[0];
    const int*   ei = (const int*)d_in[1];
    const float* W1 = (const float*)d_in[2];
    const float* b1 = (const float*)d_in[3];
    const float* W2 = (const float*)d_in[4];
    const float* b2 = (const float*)d_in[5];
    const float* W3 = (const float*)d_in[6];
    const float* b3 = (const float*)d_in[7];

    int n = in_sizes[0] / DD;
    int E = in_sizes[1] / 2;
    const int* src = ei;
    const int* dst = ei + E;

    float *y, *dinv, *ew;
    __half *x16, *act16;
    __nv_bfloat16 *whi, *wlo;
    int *cnt, *off, *cur, *esrc, *partial;
    cudaGetSymbolAddress((void**)&y, g_y);
    cudaGetSymbolAddress((void**)&x16, g_x16);
    cudaGetSymbolAddress((void**)&act16, g_act16);
    cudaGetSymbolAddress((void**)&whi, g_whi);
    cudaGetSymbolAddress((void**)&wlo, g_wlo);
    cudaGetSymbolAddress((void**)&dinv, g_dinv);
    cudaGetSymbolAddress((void**)&cnt, g_cnt);
    cudaGetSymbolAddress((void**)&off, g_off);
    cudaGetSymbolAddress((void**)&cur, g_cur);
    cudaGetSymbolAddress((void**)&esrc, g_esrc);
    cudaGetSymbolAddress((void**)&ew, g_ew);
    cudaGetSymbolAddress((void**)&partial, g_partial);

    float* outp = (float*)d_out;

    const int GEMM_SMEM = 2 * 128 * BSTRIDE_U32 * 4;
    cudaFuncSetAttribute(gemm_hmma_kernel<1, 1>, cudaFuncAttributeMaxDynamicSharedMemorySize,
                         GEMM_SMEM);
    cudaFuncSetAttribute(gemm_hmma_kernel<0, 0>, cudaFuncAttributeMaxDynamicSharedMemorySize,
                         GEMM_SMEM);

    int tb = 256;
    int np = (n + SCAN_CHUNK - 1) / SCAN_CHUNK;
    int nzb = (n + 255) / 256;
    int wsb = (3 * DD * DD + 255) / 256;
    int tot4 = n * (DD / 4);

    // --- preprocess + weight prep + x16 ---
    init_kernel<<<nzb + wsb, 256>>>(cnt, n, nzb, W1, W2, W3, whi, wlo);
    convert_x_kernel<<<(tot4 + 255) / 256, 256>>>(x, x16, tot4);
    count_kernel<<<(E + tb - 1) / tb, tb>>>(dst, cnt, E);
    scan_p1_kernel<<<np, 1024>>>(cnt, partial, n);
    scan_p3_kernel<<<np, 1024>>>(cnt, partial, off, cur, dinv, n, np);
    fill_kernel<<<(E + tb - 1) / tb, tb>>>(src, dst, dinv, cur, esrc, ew, E);

    int gemm_grid = (n + 127) / 128;
    int agg_grid = (n + 7) / 8;

    // Layer 1
    agg_kernel<<<agg_grid, 256>>>(x16, dinv, off, esrc, ew, y, n);
    gemm_hmma_kernel<1, 1><<<gemm_grid, 256, GEMM_SMEM>>>(y, whi, wlo, b1, nullptr, act16, n);
    // Layer 2
    agg_kernel<<<agg_grid, 256>>>(act16, dinv, off, esrc, ew, y, n);
    gemm_hmma_kernel<1, 1><<<gemm_grid, 256, GEMM_SMEM>>>(y, whi + DD * DD, wlo + DD * DD, b2,
                                                          nullptr, act16, n);
    // Layer 3 (no relu) -> fp32 d_out
    agg_kernel<<<agg_grid, 256>>>(act16, dinv, off, esrc, ew, y, n);
    gemm_hmma_kernel<0, 0><<<gemm_grid, 256, GEMM_SMEM>>>(y, whi + 2 * DD * DD,
                                                          wlo + 2 * DD * DD, b3, outp,
                                                          nullptr, n);
}